// round 1
// baseline (speedup 1.0000x reference)
#include <cuda_runtime.h>
#include <cuda_bf16.h>
#include <math.h>

// Problem dims (fixed by the dataset)
#define BB 32
#define SS 128
#define UU 256
#define HH 128
#define VV 30001

// Scratch (allocation-free rule: __device__ globals)
__device__ float g_state[BB * UU * HH];   // 4 MB per-(b,u) hidden state
__device__ float g_outs[BB * SS * HH];    // 2 MB RNN outputs = GEMM A

// ---------------------------------------------------------------------------
// init: copy h0 -> state
// ---------------------------------------------------------------------------
__global__ void init_state_kernel(const float* __restrict__ h0) {
    int i = blockIdx.x * blockDim.x + threadIdx.x;
    if (i < BB * UU * HH) g_state[i] = h0[i];
}

// ---------------------------------------------------------------------------
// RNN scan: one CTA per batch row, weights in SMEM (transposed, pitch-padded)
// ---------------------------------------------------------------------------
#define WPITCH 132   // 128 + 4 floats: conflict-free LDS.128 across lanes

// smem floats: WruT 256*132 | WcT 128*132 | bru 256 | bc 128 | h 128 | rh 128 | ru 256
#define RNN_SMEM_FLOATS (256 * WPITCH + 128 * WPITCH + 256 + 128 + 128 + 128 + 256)

__global__ __launch_bounds__(256, 1) void rnn_kernel(
    const int* __restrict__ users, const int* __restrict__ items,
    const float* __restrict__ P_ru, const float* __restrict__ W_ru,
    const float* __restrict__ b_ru, const float* __restrict__ P_c,
    const float* __restrict__ W_c,  const float* __restrict__ b_c)
{
    extern __shared__ float sm[];
    float* sWruT = sm;                        // [256][WPITCH] (j-major, k inner)
    float* sWcT  = sWruT + 256 * WPITCH;      // [128][WPITCH]
    float* sbru  = sWcT + 128 * WPITCH;       // [256]
    float* sbc   = sbru + 256;                // [128]
    float* sh    = sbc + 128;                 // [128]
    float* srh   = sh + 128;                  // [128]
    float* sru   = srh + 128;                 // [256]

    const int b   = blockIdx.x;
    const int tid = threadIdx.x;

    // Load weights (transposed so per-thread K access is contiguous)
    for (int k = 0; k < HH; k++)
        sWruT[tid * WPITCH + k] = W_ru[k * (2 * HH) + tid];
    if (tid < HH)
        for (int k = 0; k < HH; k++)
            sWcT[tid * WPITCH + k] = W_c[k * HH + tid];
    sbru[tid] = b_ru[tid];
    if (tid < HH) sbc[tid] = b_c[tid];
    __syncthreads();

    const int* urow = users + b * SS;
    const int* irow = items + b * SS;
    float* state_b  = g_state + b * UU * HH;
    float* out_b    = g_outs + b * SS * HH;

    for (int t = 0; t < SS; t++) {
        const int u  = urow[t];
        const int it = irow[t];

        if (tid < HH) sh[tid] = state_b[u * HH + tid];
        __syncthreads();

        // Phase 1: ru[j] = sigmoid(P_ru[it,j] + sum_k h[k]*Wru[k,j] + b_ru[j])
        {
            const int j = tid;
            float acc = P_ru[it * (2 * HH) + j] + sbru[j];
            float a0 = 0.f, a1 = 0.f, a2 = 0.f, a3 = 0.f;
            const float4* w4 = (const float4*)(sWruT + j * WPITCH);
            const float4* h4 = (const float4*)sh;
            #pragma unroll
            for (int kk = 0; kk < HH / 4; kk++) {
                float4 hv = h4[kk];
                float4 wv = w4[kk];
                a0 += hv.x * wv.x;
                a1 += hv.y * wv.y;
                a2 += hv.z * wv.z;
                a3 += hv.w * wv.w;
            }
            float x = acc + ((a0 + a1) + (a2 + a3));
            sru[j] = 1.0f / (1.0f + expf(-x));
        }
        __syncthreads();

        if (tid < HH) srh[tid] = sru[tid] * sh[tid];
        __syncthreads();

        // Phase 2: c[j] = tanh(P_c[it,j] + sum_k rh[k]*Wc[k,j] + b_c[j]); update
        if (tid < HH) {
            const int j = tid;
            float acc = P_c[it * HH + j] + sbc[j];
            float a0 = 0.f, a1 = 0.f, a2 = 0.f, a3 = 0.f;
            const float4* w4 = (const float4*)(sWcT + j * WPITCH);
            const float4* r4 = (const float4*)srh;
            #pragma unroll
            for (int kk = 0; kk < HH / 4; kk++) {
                float4 rv = r4[kk];
                float4 wv = w4[kk];
                a0 += rv.x * wv.x;
                a1 += rv.y * wv.y;
                a2 += rv.z * wv.z;
                a3 += rv.w * wv.w;
            }
            float c = tanhf(acc + ((a0 + a1) + (a2 + a3)));
            float z = sru[HH + j];
            float h = sh[j];
            float hn = z * h + (1.0f - z) * c;
            state_b[u * HH + j] = hn;
            out_b[t * HH + j]   = hn;
        }
        __syncthreads();   // order state scatter before next step's gather
    }
}

// ---------------------------------------------------------------------------
// Logits GEMM: C[4096,30001] = A[4096,128] @ ws[128,30001], tf32 mma.sync
// ---------------------------------------------------------------------------
#define APITCH 132   // pad so A-fragment LDS is conflict-free
#define BPITCH 136   // pad so B-fragment LDS is conflict-free
#define GEMM_SMEM_FLOATS (128 * APITCH + 128 * BPITCH)

__device__ __forceinline__ float to_tf32(float x) {
    float r;
    asm("cvt.rna.tf32.f32 %0, %1;" : "=f"(r) : "f"(x));
    return r;
}

__device__ __forceinline__ void mma_tf32(float c[4], const unsigned a[4],
                                         const unsigned bfr[2]) {
    asm volatile(
        "mma.sync.aligned.m16n8k8.row.col.f32.tf32.tf32.f32 "
        "{%0,%1,%2,%3}, {%4,%5,%6,%7}, {%8,%9}, {%0,%1,%2,%3};\n"
        : "+f"(c[0]), "+f"(c[1]), "+f"(c[2]), "+f"(c[3])
        : "r"(a[0]), "r"(a[1]), "r"(a[2]), "r"(a[3]), "r"(bfr[0]), "r"(bfr[1]));
}

__global__ __launch_bounds__(256, 1) void gemm_kernel(
    const float* __restrict__ ws, float* __restrict__ out)
{
    extern __shared__ float smg[];
    float* sA = smg;                  // [128][APITCH] m-major
    float* sB = smg + 128 * APITCH;   // [128][BPITCH] k-major

    const int tid = threadIdx.x;
    const int n0 = blockIdx.x * 128;
    const int m0 = blockIdx.y * 128;

    // Load A tile (tf32-rounded), vectorized: 128 rows x 128 k
    {
        const float4* A4 = (const float4*)(g_outs + (size_t)m0 * HH);
        for (int idx = tid; idx < 128 * 32; idx += 256) {
            int m  = idx >> 5;
            int k4 = idx & 31;
            float4 v = A4[m * 32 + k4];
            float* dst = sA + m * APITCH + k4 * 4;
            dst[0] = to_tf32(v.x);
            dst[1] = to_tf32(v.y);
            dst[2] = to_tf32(v.z);
            dst[3] = to_tf32(v.w);
        }
    }
    // Load B tile (ws rows are V=30001 floats -> scalar, coalesced over n)
    for (int idx = tid; idx < 128 * 128; idx += 256) {
        int k = idx >> 7;
        int n = idx & 127;
        int gn = n0 + n;
        float v = (gn < VV) ? ws[(size_t)k * VV + gn] : 0.0f;
        sB[k * BPITCH + n] = to_tf32(v);
    }
    __syncthreads();

    const int wid  = tid >> 5;
    const int lane = tid & 31;
    const int wm = (wid & 3) * 32;   // warp m-offset within tile
    const int wn = (wid >> 2) * 64;  // warp n-offset within tile
    const int lr = lane >> 2;        // groupID
    const int lc = lane & 3;         // thread-in-group

    float acc[2][8][4];
    #pragma unroll
    for (int mt = 0; mt < 2; mt++)
        #pragma unroll
        for (int nt = 0; nt < 8; nt++)
            #pragma unroll
            for (int q = 0; q < 4; q++) acc[mt][nt][q] = 0.0f;

    #pragma unroll
    for (int ks = 0; ks < 16; ks++) {
        const int k0 = ks * 8;
        unsigned a[2][4];
        #pragma unroll
        for (int mt = 0; mt < 2; mt++) {
            int r = wm + mt * 16 + lr;
            a[mt][0] = __float_as_uint(sA[r * APITCH + k0 + lc]);
            a[mt][1] = __float_as_uint(sA[(r + 8) * APITCH + k0 + lc]);
            a[mt][2] = __float_as_uint(sA[r * APITCH + k0 + lc + 4]);
            a[mt][3] = __float_as_uint(sA[(r + 8) * APITCH + k0 + lc + 4]);
        }
        unsigned bfr[8][2];
        #pragma unroll
        for (int nt = 0; nt < 8; nt++) {
            int c = wn + nt * 8 + lr;
            bfr[nt][0] = __float_as_uint(sB[(k0 + lc) * BPITCH + c]);
            bfr[nt][1] = __float_as_uint(sB[(k0 + lc + 4) * BPITCH + c]);
        }
        #pragma unroll
        for (int mt = 0; mt < 2; mt++)
            #pragma unroll
            for (int nt = 0; nt < 8; nt++)
                mma_tf32(acc[mt][nt], a[mt], bfr[nt]);
    }

    // Store (scalar: V odd so float2 would be misaligned)
    #pragma unroll
    for (int mt = 0; mt < 2; mt++) {
        #pragma unroll
        for (int nt = 0; nt < 8; nt++) {
            int r = m0 + wm + mt * 16 + lr;
            int c = n0 + wn + nt * 8 + lc * 2;
            if (c < VV) {
                out[(size_t)r * VV + c]       = acc[mt][nt][0];
                out[(size_t)(r + 8) * VV + c] = acc[mt][nt][2];
            }
            if (c + 1 < VV) {
                out[(size_t)r * VV + c + 1]       = acc[mt][nt][1];
                out[(size_t)(r + 8) * VV + c + 1] = acc[mt][nt][3];
            }
        }
    }
}

// ---------------------------------------------------------------------------
// launch
// ---------------------------------------------------------------------------
extern "C" void kernel_launch(void* const* d_in, const int* in_sizes, int n_in,
                              void* d_out, int out_size)
{
    const int*   users = (const int*)d_in[0];
    const int*   items = (const int*)d_in[1];
    const float* h0    = (const float*)d_in[2];
    const float* P_ru  = (const float*)d_in[3];
    const float* W_ru  = (const float*)d_in[4];
    const float* b_ru  = (const float*)d_in[5];
    const float* P_c   = (const float*)d_in[6];
    const float* W_c   = (const float*)d_in[7];
    const float* b_c   = (const float*)d_in[8];
    const float* ws    = (const float*)d_in[9];
    float* out = (float*)d_out;

    static_assert(RNN_SMEM_FLOATS * 4 <= 232448, "rnn smem too big");
    static_assert(GEMM_SMEM_FLOATS * 4 <= 232448, "gemm smem too big");

    cudaFuncSetAttribute(rnn_kernel, cudaFuncAttributeMaxDynamicSharedMemorySize,
                         RNN_SMEM_FLOATS * 4);
    cudaFuncSetAttribute(gemm_kernel, cudaFuncAttributeMaxDynamicSharedMemorySize,
                         GEMM_SMEM_FLOATS * 4);

    // 1) state <- h0
    init_state_kernel<<<(BB * UU * HH + 255) / 256, 256>>>(h0);

    // 2) sequential scan, one CTA per batch row
    rnn_kernel<<<BB, 256, RNN_SMEM_FLOATS * 4>>>(users, items, P_ru, W_ru, b_ru,
                                                 P_c, W_c, b_c);

    // 3) logits GEMM (tf32 tensor cores)
    dim3 grid((VV + 127) / 128, (BB * SS) / 128);
    gemm_kernel<<<grid, 256, GEMM_SMEM_FLOATS * 4>>>(ws, out);
}

// round 3
// speedup vs baseline: 1.5039x; 1.5039x over previous
#include <cuda_runtime.h>
#include <cuda_bf16.h>
#include <math.h>
#include <stdint.h>
#include <cstdint>

#define BB 32
#define SS 128
#define UU 256
#define HH 128
#define VV 30001

// Scratch (__device__ globals: allocation-free rule)
__device__ float g_state[BB * UU * HH];     // 4 MB   per-(b,u) hidden state
__device__ float g_outs[BB * SS * HH];      // 2 MB   RNN outputs (tf32-rounded) = GEMM A
__device__ float g_ws[HH * VV];             // 15.4MB ws pre-rounded to tf32

__device__ __forceinline__ float to_tf32(float x) {
    float r;
    asm("cvt.rna.tf32.f32 %0, %1;" : "=f"(r) : "f"(x));
    return r;
}

// ---------------------------------------------------------------------------
// ws -> tf32 (one pass, once per launch)
// ---------------------------------------------------------------------------
__global__ void convert_ws_kernel(const float* __restrict__ ws) {
    int i = blockIdx.x * blockDim.x + threadIdx.x;
    if (i < HH * VV) g_ws[i] = to_tf32(ws[i]);
}

// ---------------------------------------------------------------------------
// RNN scan, dependency-level batched. One CTA per batch row.
// ---------------------------------------------------------------------------
#define WPITCH 132          // 128+4 floats; conflict-free LDS.128
#define HPITCH 132
#define CH 8                // chunk size (steps processed together)

// smem floats
#define RNN_W_FLOATS   (256 * WPITCH + 128 * WPITCH + 256 + 128)
#define RNN_BUF_FLOATS (CH * HPITCH + CH * HPITCH + CH * 264)
#define RNN_INT_WORDS  (128 + 128 + 128 + 128 + 130 + 8)
#define RNN_SMEM_BYTES ((RNN_W_FLOATS + RNN_BUF_FLOATS + RNN_INT_WORDS) * 4)

__global__ __launch_bounds__(256, 1) void rnn_kernel(
    const int* __restrict__ users, const int* __restrict__ items,
    const float* __restrict__ h0,
    const float* __restrict__ P_ru, const float* __restrict__ W_ru,
    const float* __restrict__ b_ru, const float* __restrict__ P_c,
    const float* __restrict__ W_c,  const float* __restrict__ b_c)
{
    extern __shared__ float sm[];
    float* sWruT = sm;                         // [256][WPITCH] j-major
    float* sWcT  = sWruT + 256 * WPITCH;       // [128][WPITCH]
    float* sbru  = sWcT + 128 * WPITCH;        // [256]
    float* sbc   = sbru + 256;                 // [128]
    float* sH    = sbc + 128;                  // [CH][HPITCH]
    float* sRH   = sH + CH * HPITCH;           // [CH][HPITCH]
    float* sRU   = sRH + CH * HPITCH;          // [CH][264]
    int*   su      = (int*)(sRU + CH * 264);   // [128]
    int*   sit     = su + 128;                 // [128]
    int*   slev    = sit + 128;                // [128]
    int*   sorder  = slev + 128;               // [128]
    int*   slstart = sorder + 128;             // [130]
    int*   smisc   = slstart + 130;            // [8]

    const int b   = blockIdx.x;
    const int tid = threadIdx.x;

    // ---- load weights (transposed) + biases ----
    for (int k = 0; k < HH; k++)
        sWruT[tid * WPITCH + k] = W_ru[k * (2 * HH) + tid];
    if (tid < HH)
        for (int k = 0; k < HH; k++)
            sWcT[tid * WPITCH + k] = W_c[k * HH + tid];
    sbru[tid] = b_ru[tid];
    if (tid < HH) sbc[tid] = b_c[tid];

    // ---- init this row's state slice from h0 ----
    {
        const float4* src = (const float4*)(h0 + (size_t)b * UU * HH);
        float4*       dst = (float4*)(g_state + (size_t)b * UU * HH);
        for (int i = tid; i < UU * HH / 4; i += 256) dst[i] = src[i];
    }

    // ---- load indices ----
    if (tid < SS) {
        su[tid]  = users[b * SS + tid];
        sit[tid] = items[b * SS + tid];
    }
    __syncthreads();

    // ---- levels: lev[t] = #{t'<t : u[t']==u[t]} ----
    if (tid < SS) {
        int u = su[tid], c = 0;
        for (int tp = 0; tp < tid; tp++) c += (su[tp] == u);
        slev[tid] = c;
    }
    __syncthreads();

    // ---- maxlev ----
    if (tid == 0) {
        int m = 0;
        for (int t = 0; t < SS; t++) m = max(m, slev[t]);
        smisc[0] = m + 1;
    }
    // ---- levstart[l] = #{t : lev[t] < l} ----
    if (tid <= SS) {
        int c = 0;
        for (int t = 0; t < SS; t++) c += (slev[t] < tid);
        slstart[tid] = c;
    }
    __syncthreads();

    // ---- stable order by level ----
    if (tid < SS) {
        int l = slev[tid], r = 0;
        for (int tp = 0; tp < tid; tp++) r += (slev[tp] == l);
        sorder[slstart[l] + r] = tid;
    }
    __syncthreads();

    const int maxlev = smisc[0];
    float* state_b = g_state + (size_t)b * UU * HH;
    float* out_b   = g_outs + (size_t)b * SS * HH;

    const int j = tid;

    for (int l = 0; l < maxlev; l++) {
        const int lstart = slstart[l], lend = slstart[l + 1];
        for (int cs = lstart; cs < lend; cs += CH) {
            const int n = min(CH, lend - cs);

            // gather h vectors for the chunk (coalesced float4)
            for (int idx = tid; idx < n * (HH / 4); idx += 256) {
                int i  = idx >> 5;
                int q  = idx & 31;
                int t  = sorder[cs + i];
                const float4* srcs = (const float4*)(state_b + su[t] * HH);
                ((float4*)(sH + i * HPITCH))[q] = srcs[q];
            }
            __syncthreads();

            // phase 1: ru = sigmoid(P_ru[it] + h @ W_ru + b_ru), j in [0,256)
            {
                float acc[CH];
                #pragma unroll
                for (int i = 0; i < CH; i++) acc[i] = 0.0f;
                for (int i = 0; i < n; i++)
                    acc[i] = P_ru[(size_t)sit[sorder[cs + i]] * (2 * HH) + j];

                const float4* w4 = (const float4*)(sWruT + j * WPITCH);
                if (n == CH) {
                    #pragma unroll 8
                    for (int k4 = 0; k4 < HH / 4; k4++) {
                        float4 w = w4[k4];
                        #pragma unroll
                        for (int i = 0; i < CH; i++) {
                            float4 h = ((const float4*)(sH + i * HPITCH))[k4];
                            acc[i] += h.x * w.x + h.y * w.y + h.z * w.z + h.w * w.w;
                        }
                    }
                } else {
                    for (int k4 = 0; k4 < HH / 4; k4++) {
                        float4 w = w4[k4];
                        for (int i = 0; i < n; i++) {
                            float4 h = ((const float4*)(sH + i * HPITCH))[k4];
                            acc[i] += h.x * w.x + h.y * w.y + h.z * w.z + h.w * w.w;
                        }
                    }
                }
                for (int i = 0; i < n; i++) {
                    float x = acc[i] + sbru[j];
                    sRU[i * 264 + j] = 1.0f / (1.0f + expf(-x));
                }
            }
            __syncthreads();

            // rh = r * h
            for (int idx = tid; idx < n * HH; idx += 256) {
                int i = idx >> 7, jj = idx & 127;
                sRH[i * HPITCH + jj] = sRU[i * 264 + jj] * sH[i * HPITCH + jj];
            }
            __syncthreads();

            // phase 2: c = tanh(P_c[it] + rh @ W_c + b_c); h' = z h + (1-z) c
            if (j < HH) {
                float acc[CH];
                #pragma unroll
                for (int i = 0; i < CH; i++) acc[i] = 0.0f;
                for (int i = 0; i < n; i++)
                    acc[i] = P_c[(size_t)sit[sorder[cs + i]] * HH + j];

                const float4* w4 = (const float4*)(sWcT + j * WPITCH);
                if (n == CH) {
                    #pragma unroll 8
                    for (int k4 = 0; k4 < HH / 4; k4++) {
                        float4 w = w4[k4];
                        #pragma unroll
                        for (int i = 0; i < CH; i++) {
                            float4 r = ((const float4*)(sRH + i * HPITCH))[k4];
                            acc[i] += r.x * w.x + r.y * w.y + r.z * w.z + r.w * w.w;
                        }
                    }
                } else {
                    for (int k4 = 0; k4 < HH / 4; k4++) {
                        float4 w = w4[k4];
                        for (int i = 0; i < n; i++) {
                            float4 r = ((const float4*)(sRH + i * HPITCH))[k4];
                            acc[i] += r.x * w.x + r.y * w.y + r.z * w.z + r.w * w.w;
                        }
                    }
                }
                for (int i = 0; i < n; i++) {
                    int t = sorder[cs + i];
                    float c = tanhf(acc[i] + sbc[j]);
                    float z = sRU[i * 264 + HH + j];
                    float h = sH[i * HPITCH + j];
                    float hn = z * h + (1.0f - z) * c;
                    state_b[su[t] * HH + j] = hn;
                    out_b[(size_t)t * HH + j] = to_tf32(hn);
                }
            }
            __syncthreads();   // scatter visible before next chunk's gather
        }
    }
}

// ---------------------------------------------------------------------------
// Logits GEMM: C[4096,30001] = A[4096,128] @ g_ws[128,30001], tf32 mma.sync
// B-stationary: each CTA owns one 128-wide N tile, sweeps 8 M subtiles with
// cp.async double-buffered A.
// ---------------------------------------------------------------------------
#define APITCH 132
#define BPITCH 136
#define GEMM_SMEM_FLOATS (128 * BPITCH + 2 * 128 * APITCH)

__device__ __forceinline__ void cp_async16(uint32_t saddr, const void* gsrc) {
    asm volatile("cp.async.cg.shared.global [%0], [%1], 16;\n" :: "r"(saddr), "l"(gsrc));
}
__device__ __forceinline__ void cp_commit() {
    asm volatile("cp.async.commit_group;\n");
}
__device__ __forceinline__ void cp_wait0() {
    asm volatile("cp.async.wait_group 0;\n");
}

__device__ __forceinline__ void mma_tf32(float c[4], const unsigned a[4],
                                         const unsigned bfr[2]) {
    asm volatile(
        "mma.sync.aligned.m16n8k8.row.col.f32.tf32.tf32.f32 "
        "{%0,%1,%2,%3}, {%4,%5,%6,%7}, {%8,%9}, {%0,%1,%2,%3};\n"
        : "+f"(c[0]), "+f"(c[1]), "+f"(c[2]), "+f"(c[3])
        : "r"(a[0]), "r"(a[1]), "r"(a[2]), "r"(a[3]), "r"(bfr[0]), "r"(bfr[1]));
}

__global__ __launch_bounds__(256, 1) void gemm_kernel(float* __restrict__ out)
{
    extern __shared__ float smg[];
    float* sB = smg;                      // [128][BPITCH] k-major
    float* sA = smg + 128 * BPITCH;       // [2][128][APITCH]

    const int tid = threadIdx.x;
    const int n0  = blockIdx.x * 128;
    const int mg  = blockIdx.y * 1024;    // 8 subtiles of 128 rows

    uint32_t sA_base = (uint32_t)__cvta_generic_to_shared(sA);

    // prefetch A subtile 0 into buf 0
    {
        const float* src = g_outs + (size_t)mg * HH;
        for (int idx = tid; idx < 128 * 32; idx += 256) {
            int row = idx >> 5, q = idx & 31;
            cp_async16(sA_base + (row * APITCH + q * 4) * 4, src + row * HH + q * 4);
        }
        cp_commit();
    }

    // load B tile once (already tf32)
    for (int idx = tid; idx < 128 * 128; idx += 256) {
        int k = idx >> 7, n = idx & 127;
        int gn = n0 + n;
        sB[k * BPITCH + n] = (gn < VV) ? g_ws[(size_t)k * VV + gn] : 0.0f;
    }

    const int wid  = tid >> 5;
    const int lane = tid & 31;
    const int wm = (wid & 3) * 32;
    const int wn = (wid >> 2) * 64;
    const int lr = lane >> 2;
    const int lc = lane & 3;

    cp_wait0();
    __syncthreads();

    int buf = 0;
    for (int msub = 0; msub < 8; msub++) {
        // prefetch next A subtile into the other buffer
        if (msub < 7) {
            const float* src = g_outs + (size_t)(mg + (msub + 1) * 128) * HH;
            uint32_t dstb = sA_base + (uint32_t)(buf ^ 1) * 128u * APITCH * 4u;
            for (int idx = tid; idx < 128 * 32; idx += 256) {
                int row = idx >> 5, q = idx & 31;
                cp_async16(dstb + (row * APITCH + q * 4) * 4, src + row * HH + q * 4);
            }
            cp_commit();
        }

        float* sAc = sA + buf * 128 * APITCH;

        float acc[2][8][4];
        #pragma unroll
        for (int mt = 0; mt < 2; mt++)
            #pragma unroll
            for (int nt = 0; nt < 8; nt++)
                #pragma unroll
                for (int q = 0; q < 4; q++) acc[mt][nt][q] = 0.0f;

        #pragma unroll
        for (int ks = 0; ks < 16; ks++) {
            const int k0 = ks * 8;
            unsigned a[2][4];
            #pragma unroll
            for (int mt = 0; mt < 2; mt++) {
                int r = wm + mt * 16 + lr;
                a[mt][0] = __float_as_uint(sAc[r * APITCH + k0 + lc]);
                a[mt][1] = __float_as_uint(sAc[(r + 8) * APITCH + k0 + lc]);
                a[mt][2] = __float_as_uint(sAc[r * APITCH + k0 + lc + 4]);
                a[mt][3] = __float_as_uint(sAc[(r + 8) * APITCH + k0 + lc + 4]);
            }
            unsigned bfr[8][2];
            #pragma unroll
            for (int nt = 0; nt < 8; nt++) {
                int c = wn + nt * 8 + lr;
                bfr[nt][0] = __float_as_uint(sB[(k0 + lc) * BPITCH + c]);
                bfr[nt][1] = __float_as_uint(sB[(k0 + lc + 4) * BPITCH + c]);
            }
            #pragma unroll
            for (int mt = 0; mt < 2; mt++)
                #pragma unroll
                for (int nt = 0; nt < 8; nt++)
                    mma_tf32(acc[mt][nt], a[mt], bfr[nt]);
        }

        // store this subtile
        const int m0 = mg + msub * 128;
        #pragma unroll
        for (int mt = 0; mt < 2; mt++) {
            #pragma unroll
            for (int nt = 0; nt < 8; nt++) {
                int r = m0 + wm + mt * 16 + lr;
                int c = n0 + wn + nt * 8 + lc * 2;
                if (c < VV) {
                    out[(size_t)r * VV + c]       = acc[mt][nt][0];
                    out[(size_t)(r + 8) * VV + c] = acc[mt][nt][2];
                }
                if (c + 1 < VV) {
                    out[(size_t)r * VV + c + 1]       = acc[mt][nt][1];
                    out[(size_t)(r + 8) * VV + c + 1] = acc[mt][nt][3];
                }
            }
        }

        cp_wait0();
        __syncthreads();   // next iteration overwrites buf^1 only after all reads
        buf ^= 1;
    }
}

// ---------------------------------------------------------------------------
// launch
// ---------------------------------------------------------------------------
extern "C" void kernel_launch(void* const* d_in, const int* in_sizes, int n_in,
                              void* d_out, int out_size)
{
    const int*   users = (const int*)d_in[0];
    const int*   items = (const int*)d_in[1];
    const float* h0    = (const float*)d_in[2];
    const float* P_ru  = (const float*)d_in[3];
    const float* W_ru  = (const float*)d_in[4];
    const float* b_ru  = (const float*)d_in[5];
    const float* P_c   = (const float*)d_in[6];
    const float* W_c   = (const float*)d_in[7];
    const float* b_c   = (const float*)d_in[8];
    const float* ws    = (const float*)d_in[9];
    float* out = (float*)d_out;

    static_assert(RNN_SMEM_BYTES <= 232448, "rnn smem too big");
    static_assert(GEMM_SMEM_FLOATS * 4 <= 232448, "gemm smem too big");

    cudaFuncSetAttribute(rnn_kernel, cudaFuncAttributeMaxDynamicSharedMemorySize,
                         RNN_SMEM_BYTES);
    cudaFuncSetAttribute(gemm_kernel, cudaFuncAttributeMaxDynamicSharedMemorySize,
                         GEMM_SMEM_FLOATS * 4);

    convert_ws_kernel<<<(HH * VV + 255) / 256, 256>>>(ws);

    rnn_kernel<<<BB, 256, RNN_SMEM_BYTES>>>(users, items, h0, P_ru, W_ru, b_ru,
                                            P_c, W_c, b_c);

    dim3 grid((VV + 127) / 128, 4);
    gemm_kernel<<<grid, 256, GEMM_SMEM_FLOATS * 4>>>(out);
}

// round 8
// speedup vs baseline: 1.5554x; 1.0342x over previous
#include <cuda_runtime.h>
#include <math.h>
#include <stdint.h>

#define BB 32
#define SS 128
#define UU 256
#define HH 128
#define VV 30001

// Scratch (__device__ globals: allocation-free rule)
__device__ float g_state[BB * UU * HH];   // per-(b,u) hidden state
__device__ float g_outs[BB * SS * HH];    // RNN outputs (tf32-rounded) = GEMM A

__device__ __forceinline__ float to_tf32(float x) {
    float r;
    asm("cvt.rna.tf32.f32 %0, %1;" : "=f"(r) : "f"(x));
    return r;
}

// f32x2 packed math (sm_103a)
__device__ __forceinline__ unsigned long long pack2(float lo, float hi) {
    unsigned long long d;
    asm("mov.b64 %0, {%1, %2};" : "=l"(d) : "f"(lo), "f"(hi));
    return d;
}
__device__ __forceinline__ void unpack2(unsigned long long v, float& lo, float& hi) {
    asm("mov.b64 {%0, %1}, %2;" : "=f"(lo), "=f"(hi) : "l"(v));
}
__device__ __forceinline__ void fma2(unsigned long long& d, unsigned long long a,
                                     unsigned long long b) {
    asm("fma.rn.f32x2 %0, %1, %2, %0;" : "+l"(d) : "l"(a), "l"(b));
}

// ---------------------------------------------------------------------------
// RNN scan, dependency-level batched, FFMA2. One CTA per batch row.
// ---------------------------------------------------------------------------
#define CH 16          // steps per chunk
#define TP 20          // transposed-buffer pitch ([k][i] arrays)

#define RNN_F_WRU   (128 * 256)
#define RNN_F_WC    (128 * 128)
#define RNN_F_BUFS  (3 * 128 * TP)
#define RNN_INTS    (128 + 128 + 128 + 128 + 130 + 8)
#define RNN_SMEM_BYTES ((RNN_F_WRU + RNN_F_WC + 256 + 128 + RNN_F_BUFS + RNN_INTS) * 4)

__global__ __launch_bounds__(256, 1) void rnn_kernel(
    const int* __restrict__ users, const int* __restrict__ items,
    const float* __restrict__ h0,
    const float* __restrict__ P_ru, const float* __restrict__ W_ru,
    const float* __restrict__ b_ru, const float* __restrict__ P_c,
    const float* __restrict__ W_c,  const float* __restrict__ b_c)
{
    extern __shared__ float sm[];
    float* sWru = sm;                          // [128][256] k-major (native layout)
    float* sWc  = sWru + RNN_F_WRU;            // [128][128] k-major
    float* sbru = sWc + RNN_F_WC;              // [256]
    float* sbc  = sbru + 256;                  // [128]
    float* sHT  = sbc + 128;                   // [128][TP]: sHT[k*TP+i] = h_i[k]
    float* sRHT = sHT + 128 * TP;              // [128][TP]: rh transposed
    float* sZT  = sRHT + 128 * TP;             // [128][TP]: sZT[j*TP+i] = z_i[j]
    int*   su      = (int*)(sZT + 128 * TP);   // [128]
    int*   sit     = su + 128;
    int*   slev    = sit + 128;
    int*   sorder  = slev + 128;
    int*   slstart = sorder + 128;             // [130]
    int*   smisc   = slstart + 130;            // [8]

    const int b   = blockIdx.x;
    const int tid = threadIdx.x;

    // ---- weights: straight float4 copies (same layout as source) ----
    {
        const float4* s4 = (const float4*)W_ru;
        float4*       d4 = (float4*)sWru;
        for (int i = tid; i < RNN_F_WRU / 4; i += 256) d4[i] = s4[i];
        const float4* s4c = (const float4*)W_c;
        float4*       d4c = (float4*)sWc;
        for (int i = tid; i < RNN_F_WC / 4; i += 256) d4c[i] = s4c[i];
    }
    sbru[tid] = b_ru[tid];
    if (tid < HH) sbc[tid] = b_c[tid];

    // zero transposed buffers
    for (int i = tid; i < 3 * 128 * TP; i += 256) sHT[i] = 0.0f;

    // ---- init this row's state slice from h0 ----
    {
        const float4* src = (const float4*)(h0 + (size_t)b * UU * HH);
        float4*       dst = (float4*)(g_state + (size_t)b * UU * HH);
        for (int i = tid; i < UU * HH / 4; i += 256) dst[i] = src[i];
    }

    // ---- indices ----
    if (tid < SS) {
        su[tid]  = users[b * SS + tid];
        sit[tid] = items[b * SS + tid];
    }
    __syncthreads();

    // ---- levels: lev[t] = #{t'<t : u[t']==u[t]} ----
    if (tid < SS) {
        int u = su[tid], c = 0;
        for (int tp = 0; tp < tid; tp++) c += (su[tp] == u);
        slev[tid] = c;
    }
    __syncthreads();
    if (tid == 0) {
        int m = 0;
        for (int t = 0; t < SS; t++) m = max(m, slev[t]);
        smisc[0] = m + 1;
    }
    if (tid <= SS) {
        int c = 0;
        for (int t = 0; t < SS; t++) c += (slev[t] < tid);
        slstart[tid] = c;
    }
    __syncthreads();
    if (tid < SS) {
        int l = slev[tid], r = 0;
        for (int tp = 0; tp < tid; tp++) r += (slev[tp] == l);
        sorder[slstart[l] + r] = tid;
    }
    __syncthreads();

    const int maxlev = smisc[0];
    float* state_b = g_state + (size_t)b * UU * HH;
    float* out_b   = g_outs + (size_t)b * SS * HH;
    const int j = tid;

    for (int l = 0; l < maxlev; l++) {
        const int lstart = slstart[l], lend = slstart[l + 1];
        for (int cs = lstart; cs < lend; cs += CH) {
            const int n = min(CH, lend - cs);

            // ---- gather: each thread covers TWO float4s -> full k=0..127 ----
            {
                int i      = tid & 15;
                int r4base = tid >> 4;         // 0..15
                if (i < n) {
                    int t = sorder[cs + i];
                    const float4* srcs = (const float4*)(state_b + su[t] * HH);
                    #pragma unroll
                    for (int rr = 0; rr < 2; rr++) {
                        int r4 = r4base + rr * 16;     // 0..31 -> k0 = r4*4
                        float4 v = srcs[r4];
                        int k0 = r4 * 4;
                        sHT[(k0 + 0) * TP + i] = v.x;
                        sHT[(k0 + 1) * TP + i] = v.y;
                        sHT[(k0 + 2) * TP + i] = v.z;
                        sHT[(k0 + 3) * TP + i] = v.w;
                    }
                }
            }
            __syncthreads();

            // ---- phase 1: ru = sigmoid(P_ru[it] + h @ W_ru + b_ru), j in [0,256) ----
            {
                float pAdd[CH];
                #pragma unroll
                for (int i = 0; i < CH; i++) pAdd[i] = 0.0f;
                for (int i = 0; i < n; i++)
                    pAdd[i] = P_ru[(size_t)sit[sorder[cs + i]] * (2 * HH) + j];

                unsigned long long acc2[CH / 2];
                #pragma unroll
                for (int p = 0; p < CH / 2; p++) acc2[p] = 0ULL;

                #pragma unroll 4
                for (int k = 0; k < HH; k++) {
                    float w = sWru[k * 256 + j];
                    unsigned long long w2 = pack2(w, w);
                    const ulonglong2* h4 = (const ulonglong2*)(sHT + k * TP);
                    #pragma unroll
                    for (int q = 0; q < CH / 4; q++) {
                        ulonglong2 hp = h4[q];
                        fma2(acc2[2 * q],     hp.x, w2);
                        fma2(acc2[2 * q + 1], hp.y, w2);
                    }
                }

                float bj = sbru[j];
                if (j < HH) {
                    #pragma unroll
                    for (int p = 0; p < CH / 2; p++) {
                        float a0, a1;
                        unpack2(acc2[p], a0, a1);
                        float x0 = fminf(fmaxf(a0 + pAdd[2 * p] + bj,     -15.f), 15.f);
                        float x1 = fminf(fmaxf(a1 + pAdd[2 * p + 1] + bj, -15.f), 15.f);
                        float r0 = __fdividef(1.0f, 1.0f + __expf(-x0));
                        float r1 = __fdividef(1.0f, 1.0f + __expf(-x1));
                        sRHT[j * TP + 2 * p]     = r0 * sHT[j * TP + 2 * p];
                        sRHT[j * TP + 2 * p + 1] = r1 * sHT[j * TP + 2 * p + 1];
                    }
                } else {
                    int jz = j - HH;
                    #pragma unroll
                    for (int p = 0; p < CH / 2; p++) {
                        float a0, a1;
                        unpack2(acc2[p], a0, a1);
                        float x0 = fminf(fmaxf(a0 + pAdd[2 * p] + bj,     -15.f), 15.f);
                        float x1 = fminf(fmaxf(a1 + pAdd[2 * p + 1] + bj, -15.f), 15.f);
                        sZT[jz * TP + 2 * p]     = __fdividef(1.0f, 1.0f + __expf(-x0));
                        sZT[jz * TP + 2 * p + 1] = __fdividef(1.0f, 1.0f + __expf(-x1));
                    }
                }
            }
            __syncthreads();

            // ---- phase 2: c = tanh(P_c[it] + rh @ W_c + b_c); h' = z h + (1-z) c ----
            if (j < HH) {
                float pAdd[CH];
                #pragma unroll
                for (int i = 0; i < CH; i++) pAdd[i] = 0.0f;
                for (int i = 0; i < n; i++)
                    pAdd[i] = P_c[(size_t)sit[sorder[cs + i]] * HH + j];

                unsigned long long acc2[CH / 2];
                #pragma unroll
                for (int p = 0; p < CH / 2; p++) acc2[p] = 0ULL;

                #pragma unroll 4
                for (int k = 0; k < HH; k++) {
                    float w = sWc[k * 128 + j];
                    unsigned long long w2 = pack2(w, w);
                    const ulonglong2* r4 = (const ulonglong2*)(sRHT + k * TP);
                    #pragma unroll
                    for (int q = 0; q < CH / 4; q++) {
                        ulonglong2 rp = r4[q];
                        fma2(acc2[2 * q],     rp.x, w2);
                        fma2(acc2[2 * q + 1], rp.y, w2);
                    }
                }

                float bj = sbc[j];
                float cc[CH];
                #pragma unroll
                for (int p = 0; p < CH / 2; p++) {
                    float a0, a1;
                    unpack2(acc2[p], a0, a1);
                    float x0 = fminf(fmaxf(a0 + pAdd[2 * p] + bj,     -15.f), 15.f);
                    float x1 = fminf(fmaxf(a1 + pAdd[2 * p + 1] + bj, -15.f), 15.f);
                    float t0 = __expf(-2.0f * x0);
                    float t1 = __expf(-2.0f * x1);
                    cc[2 * p]     = __fdividef(1.0f - t0, 1.0f + t0);
                    cc[2 * p + 1] = __fdividef(1.0f - t1, 1.0f + t1);
                }
                for (int i = 0; i < n; i++) {
                    int t = sorder[cs + i];
                    float z = sZT[j * TP + i];
                    float h = sHT[j * TP + i];
                    float hn = z * h + (1.0f - z) * cc[i];
                    state_b[su[t] * HH + j] = hn;
                    out_b[(size_t)t * HH + j] = to_tf32(hn);
                }
            }
            __syncthreads();   // scatter visible before next chunk's gather
        }
    }
}

// ---------------------------------------------------------------------------
// Logits GEMM: C[4096,30001] = A[4096,128] @ tf32(ws[128,30001]), mma.sync
// B-stationary; cp.async double-buffered A; ws converted in-flight.
// ---------------------------------------------------------------------------
#define APITCH 132
#define BPITCH 136
#define GEMM_SMEM_FLOATS (128 * BPITCH + 2 * 128 * APITCH)

__device__ __forceinline__ void cp_async16(uint32_t saddr, const void* gsrc) {
    asm volatile("cp.async.cg.shared.global [%0], [%1], 16;\n" :: "r"(saddr), "l"(gsrc));
}
__device__ __forceinline__ void cp_commit() {
    asm volatile("cp.async.commit_group;\n");
}
__device__ __forceinline__ void cp_wait0() {
    asm volatile("cp.async.wait_group 0;\n");
}

__device__ __forceinline__ void mma_tf32(float c[4], const unsigned a[4],
                                         const unsigned bfr[2]) {
    asm volatile(
        "mma.sync.aligned.m16n8k8.row.col.f32.tf32.tf32.f32 "
        "{%0,%1,%2,%3}, {%4,%5,%6,%7}, {%8,%9}, {%0,%1,%2,%3};\n"
        : "+f"(c[0]), "+f"(c[1]), "+f"(c[2]), "+f"(c[3])
        : "r"(a[0]), "r"(a[1]), "r"(a[2]), "r"(a[3]), "r"(bfr[0]), "r"(bfr[1]));
}

__global__ __launch_bounds__(256, 1) void gemm_kernel(const float* __restrict__ ws,
                                                      float* __restrict__ out)
{
    extern __shared__ float smg[];
    float* sB = smg;                      // [128][BPITCH] k-major
    float* sA = smg + 128 * BPITCH;       // [2][128][APITCH]

    const int tid = threadIdx.x;
    const int n0  = blockIdx.x * 128;
    const int mg  = blockIdx.y * 1024;    // 8 subtiles of 128 rows

    uint32_t sA_base = (uint32_t)__cvta_generic_to_shared(sA);

    // prefetch A subtile 0 into buf 0
    {
        const float* src = g_outs + (size_t)mg * HH;
        for (int idx = tid; idx < 128 * 32; idx += 256) {
            int row = idx >> 5, q = idx & 31;
            cp_async16(sA_base + (row * APITCH + q * 4) * 4, src + row * HH + q * 4);
        }
        cp_commit();
    }

    // load B tile once, converting to tf32 in-flight
    for (int idx = tid; idx < 128 * 128; idx += 256) {
        int k = idx >> 7, n = idx & 127;
        int gn = n0 + n;
        float v = (gn < VV) ? ws[(size_t)k * VV + gn] : 0.0f;
        sB[k * BPITCH + n] = to_tf32(v);
    }

    const int wid  = tid >> 5;
    const int lane = tid & 31;
    const int wm = (wid & 3) * 32;
    const int wn = (wid >> 2) * 64;
    const int lr = lane >> 2;
    const int lc = lane & 3;

    cp_wait0();
    __syncthreads();

    int buf = 0;
    for (int msub = 0; msub < 8; msub++) {
        if (msub < 7) {
            const float* src = g_outs + (size_t)(mg + (msub + 1) * 128) * HH;
            uint32_t dstb = sA_base + (uint32_t)(buf ^ 1) * 128u * APITCH * 4u;
            for (int idx = tid; idx < 128 * 32; idx += 256) {
                int row = idx >> 5, q = idx & 31;
                cp_async16(dstb + (row * APITCH + q * 4) * 4, src + row * HH + q * 4);
            }
            cp_commit();
        }

        float* sAc = sA + buf * 128 * APITCH;

        float acc[2][8][4];
        #pragma unroll
        for (int mt = 0; mt < 2; mt++)
            #pragma unroll
            for (int nt = 0; nt < 8; nt++)
                #pragma unroll
                for (int q = 0; q < 4; q++) acc[mt][nt][q] = 0.0f;

        #pragma unroll
        for (int ks = 0; ks < 16; ks++) {
            const int k0 = ks * 8;
            unsigned a[2][4];
            #pragma unroll
            for (int mt = 0; mt < 2; mt++) {
                int r = wm + mt * 16 + lr;
                a[mt][0] = __float_as_uint(sAc[r * APITCH + k0 + lc]);
                a[mt][1] = __float_as_uint(sAc[(r + 8) * APITCH + k0 + lc]);
                a[mt][2] = __float_as_uint(sAc[r * APITCH + k0 + lc + 4]);
                a[mt][3] = __float_as_uint(sAc[(r + 8) * APITCH + k0 + lc + 4]);
            }
            unsigned bfr[8][2];
            #pragma unroll
            for (int nt = 0; nt < 8; nt++) {
                int c = wn + nt * 8 + lr;
                bfr[nt][0] = __float_as_uint(sB[(k0 + lc) * BPITCH + c]);
                bfr[nt][1] = __float_as_uint(sB[(k0 + lc + 4) * BPITCH + c]);
            }
            #pragma unroll
            for (int mt = 0; mt < 2; mt++)
                #pragma unroll
                for (int nt = 0; nt < 8; nt++)
                    mma_tf32(acc[mt][nt], a[mt], bfr[nt]);
        }

        const int m0 = mg + msub * 128;
        #pragma unroll
        for (int mt = 0; mt < 2; mt++) {
            #pragma unroll
            for (int nt = 0; nt < 8; nt++) {
                int r = m0 + wm + mt * 16 + lr;
                int c = n0 + wn + nt * 8 + lc * 2;
                if (c < VV) {
                    out[(size_t)r * VV + c]       = acc[mt][nt][0];
                    out[(size_t)(r + 8) * VV + c] = acc[mt][nt][2];
                }
                if (c + 1 < VV) {
                    out[(size_t)r * VV + c + 1]       = acc[mt][nt][1];
                    out[(size_t)(r + 8) * VV + c + 1] = acc[mt][nt][3];
                }
            }
        }

        cp_wait0();
        __syncthreads();
        buf ^= 1;
    }
}

// ---------------------------------------------------------------------------
// launch
// ---------------------------------------------------------------------------
extern "C" void kernel_launch(void* const* d_in, const int* in_sizes, int n_in,
                              void* d_out, int out_size)
{
    const int*   users = (const int*)d_in[0];
    const int*   items = (const int*)d_in[1];
    const float* h0    = (const float*)d_in[2];
    const float* P_ru  = (const float*)d_in[3];
    const float* W_ru  = (const float*)d_in[4];
    const float* b_ru  = (const float*)d_in[5];
    const float* P_c   = (const float*)d_in[6];
    const float* W_c   = (const float*)d_in[7];
    const float* b_c   = (const float*)d_in[8];
    const float* ws    = (const float*)d_in[9];
    float* out = (float*)d_out;

    static_assert(RNN_SMEM_BYTES <= 232448, "rnn smem too big");
    static_assert(GEMM_SMEM_FLOATS * 4 <= 232448, "gemm smem too big");

    cudaFuncSetAttribute(rnn_kernel, cudaFuncAttributeMaxDynamicSharedMemorySize,
                         RNN_SMEM_BYTES);
    cudaFuncSetAttribute(gemm_kernel, cudaFuncAttributeMaxDynamicSharedMemorySize,
                         GEMM_SMEM_FLOATS * 4);

    rnn_kernel<<<BB, 256, RNN_SMEM_BYTES>>>(users, items, h0, P_ru, W_ru, b_ru,
                                            P_c, W_c, b_c);

    dim3 grid((VV + 127) / 128, 4);
    gemm_kernel<<<grid, 256, GEMM_SMEM_FLOATS * 4>>>(ws, out);
}